// round 15
// baseline (speedup 1.0000x reference)
#include <cuda_runtime.h>

// Bilateral filter, B=2 C=3 H=W=384, ksize=9, sigma=1.7.
// Density exp ~ minimax linear poly in u=(v-c)^2 on [0,1]; filter = separable
// 9-tap Gaussian moments M1,M2,M3:
//   den = b1*M2 + (-2*b1*c)*M1 + (b0+b1*c^2)*S2
//   num = b1*M3 + (-2*b1*c)*M2 + (b0+b1*c^2)*M1
// FUSED STRUCTURE: horizontal pass reads its windows straight from GMEM
// (no raw smem tile, no load barrier); only the 3 moment planes live in
// smem; single __syncthreads. Packed f32x2 lanes = adjacent columns.

#define TW   64
#define TH   32
#define HALO 4
#define SWY  40
#define KS   9

typedef unsigned long long u64;

// exp(-A*d*d), A = 1/(2*1.7^2)
#define G0f 1.00000000f
#define G1f 0.84112888f
#define G2f 0.50055313f
#define G3f 0.21074770f
#define G4f 0.06277701f
#define S2f 17.8963970f
// minimax linear for exp(-A*u), u in [0,1]
#define B0f 0.99828148f
#define B1f (-0.15887112f)

__device__ __forceinline__ u64 pack2(float lo, float hi) {
    u64 r; asm("mov.b64 %0, {%1,%2};" : "=l"(r) : "f"(lo), "f"(hi)); return r;
}
__device__ __forceinline__ void unpack2(u64 v, float& lo, float& hi) {
    asm("mov.b64 {%0,%1}, %2;" : "=f"(lo), "=f"(hi) : "l"(v));
}
__device__ __forceinline__ u64 fma2(u64 a, u64 b, u64 c) {
    u64 d; asm("fma.rn.f32x2 %0, %1, %2, %3;" : "=l"(d) : "l"(a), "l"(b), "l"(c)); return d;
}
__device__ __forceinline__ u64 mul2(u64 a, u64 b) {
    u64 d; asm("mul.rn.f32x2 %0, %1, %2;" : "=l"(d) : "l"(a), "l"(b)); return d;
}

__global__ __launch_bounds__(256)
void bilateral9_kernel(const float* __restrict__ x, float* __restrict__ out,
                       int H, int W) {
    __shared__ __align__(16) float pM1[SWY][TW];     // 10 KB
    __shared__ __align__(16) float pM2[SWY][TW];     // 10 KB
    __shared__ __align__(16) float pM3[SWY][TW];     // 10 KB

    const int plane = blockIdx.z;
    const float* xp = x + (size_t)plane * H * W;
    float* op = out + (size_t)plane * H * W;
    const int x0 = blockIdx.x * TW;
    const int y0 = blockIdx.y * TH;
    const int tid = threadIdx.x;

    const u64 GG[5] = { pack2(G0f, G0f), pack2(G1f, G1f), pack2(G2f, G2f),
                        pack2(G3f, G3f), pack2(G4f, G4f) };

    const bool interior = (x0 >= HALO) && (x0 + TW + HALO <= W) &&
                          (y0 >= HALO) && (y0 + TH + HALO <= H);

    // ---- horizontal pass straight from GMEM ----
    // 40 rows x 32 col-pairs = 1280 units = 5 per thread.
    {
        const int cp  = tid & 31;        // cols 2cp, 2cp+1 of the tile
        const int rid = tid >> 5;        // 0..7
        #pragma unroll
        for (int rr = 0; rr < 5; rr++) {
            const int r = rid + rr * 8;
            u64 V[9];
            if (interior) {
                const float* gptr = xp + (size_t)(y0 + r - HALO) * W
                                       + (x0 + 2 * cp - HALO);
                float2 L0 = *(const float2*)(gptr + 0);
                float2 L1 = *(const float2*)(gptr + 2);
                float2 L2 = *(const float2*)(gptr + 4);
                float2 L3 = *(const float2*)(gptr + 6);
                float2 L4 = *(const float2*)(gptr + 8);
                V[0] = pack2(L0.x, L0.y);
                V[1] = pack2(L0.y, L1.x);
                V[2] = pack2(L1.x, L1.y);
                V[3] = pack2(L1.y, L2.x);
                V[4] = pack2(L2.x, L2.y);
                V[5] = pack2(L2.y, L3.x);
                V[6] = pack2(L3.x, L3.y);
                V[7] = pack2(L3.y, L4.x);
                V[8] = pack2(L4.x, L4.y);
            } else {
                int gy = y0 + r - HALO;
                gy = gy < 0 ? -gy : (gy >= H ? 2 * H - 2 - gy : gy);
                const float* rowp = xp + (size_t)gy * W;
                float f[10];
                #pragma unroll
                for (int i = 0; i < 10; i++) {
                    int gx = x0 + 2 * cp - HALO + i;
                    gx = gx < 0 ? -gx : (gx >= W ? 2 * W - 2 - gx : gx);
                    f[i] = rowp[gx];
                }
                #pragma unroll
                for (int j = 0; j < 9; j++) V[j] = pack2(f[j], f[j + 1]);
            }

            u64 a1, a2, a3;
            {   // j = 0, weight g4
                u64 vv = V[0];
                u64 v2 = mul2(vv, vv), v3 = mul2(v2, vv);
                a1 = mul2(GG[4], vv);
                a2 = mul2(GG[4], v2);
                a3 = mul2(GG[4], v3);
            }
            #pragma unroll
            for (int j = 1; j < KS; j++) {
                u64 vv = V[j];
                u64 v2 = mul2(vv, vv), v3 = mul2(v2, vv);
                const u64 g = GG[j < 4 ? 4 - j : j - 4];
                a1 = fma2(g, vv, a1);
                a2 = fma2(g, v2, a2);
                a3 = fma2(g, v3, a3);
            }

            // packed lanes == adjacent columns: store directly
            *(u64*)&pM1[r][2 * cp] = a1;
            *(u64*)&pM2[r][2 * cp] = a2;
            *(u64*)&pM3[r][2 * cp] = a3;
        }
    }
    __syncthreads();

    // ---- vertical pass + epilogue: packed column pairs ----
    const int cp = tid & 31;             // col-pair 0..31
    const int rg = tid >> 5;             // 0..7 -> output rows rg*4 .. rg*4+3

    const u64 B0p  = pack2(B0f, B0f);
    const u64 B1p  = pack2(B1f, B1f);
    const u64 N2B1 = pack2(-2.0f * B1f, -2.0f * B1f);
    const u64 S2p  = pack2(S2f, S2f);

    // two groups of 2 output rows each -> only 6 live u64 accumulators
    #pragma unroll
    for (int gpi = 0; gpi < 2; gpi++) {
        const int rbase = rg * 4 + gpi * 2;   // first output row of group
        u64 m1[2], m2[2], m3[2];
        #pragma unroll
        for (int p = 0; p < 2; p++) { m1[p] = 0ull; m2[p] = 0ull; m3[p] = 0ull; }

        #pragma unroll
        for (int r = 0; r < 10; r++) {        // rows rbase .. rbase+9
            const int row = rbase + r;
            u64 h1 = *(const u64*)&pM1[row][2 * cp];
            u64 h2 = *(const u64*)&pM2[row][2 * cp];
            u64 h3 = *(const u64*)&pM3[row][2 * cp];
            #pragma unroll
            for (int p = 0; p < 2; p++) {
                const int t = r - p;
                if (t >= 0 && t < KS) {       // compile-time pruned
                    const int d = t < 4 ? 4 - t : t - 4;
                    m1[p] = fma2(GG[d], h1, m1[p]);
                    m2[p] = fma2(GG[d], h2, m2[p]);
                    m3[p] = fma2(GG[d], h3, m3[p]);
                }
            }
        }

        #pragma unroll
        for (int p = 0; p < 2; p++) {
            const int row = rbase + p;
            // center values: coalesced, always in-bounds
            float2 cc = *(const float2*)(xp + (size_t)(y0 + row) * W
                                            + (x0 + 2 * cp));
            u64 c  = pack2(cc.x, cc.y);
            u64 c2 = mul2(c, c);
            u64 p1 = mul2(N2B1, c);                    // -2*b1*c
            u64 q  = fma2(B1p, c2, B0p);               // b0 + b1*c^2

            u64 den = fma2(q, S2p, fma2(p1, m1[p], mul2(B1p, m2[p])));
            u64 num = fma2(q, m1[p], fma2(p1, m2[p], mul2(B1p, m3[p])));

            float n0, n1, d0, d1;
            unpack2(num, n0, n1);
            unpack2(den, d0, d1);
            float2 o = make_float2(__fdividef(n0, d0), __fdividef(n1, d1));
            int oy = y0 + row;
            *(float2*)&op[(size_t)oy * W + x0 + 2 * cp] = o;
        }
    }
}

extern "C" void kernel_launch(void* const* d_in, const int* in_sizes, int n_in,
                              void* d_out, int out_size) {
    const float* x = (const float*)d_in[0];
    float* out = (float*)d_out;
    const int H = 384, W = 384;
    const int planes = out_size / (H * W);   // B*C = 6

    dim3 block(256, 1, 1);
    dim3 grid(W / TW, H / TH, planes);
    bilateral9_kernel<<<grid, block>>>(x, out, H, W);
}

// round 16
// speedup vs baseline: 1.1797x; 1.1797x over previous
#include <cuda_runtime.h>

// Bilateral filter, B=2 C=3 H=W=384, ksize=9, sigma=1.7.
// Density exp ~ minimax linear poly in u=(v-c)^2 on [0,1]; filter = separable
// 9-tap Gaussian moments M1,M2,M3:
//   den = b1*M2 + (-2*b1*c)*M1 + (b0+b1*c^2)*S2
//   num = b1*M3 + (-2*b1*c)*M2 + (b0+b1*c^2)*M1
// Scalar FFMA body (weights are FFMA-imm, rt=1), 512-thread CTAs for
// latency hiding (12 warps/SMSP), vertical in col-pair float2 units with
// 2 output rows per thread (keeps plane reuse at R13 levels).

#define TW   64
#define TH   32
#define HALO 4
#define SWX  72
#define SWXP 76          // raw row stride in floats (304B, 16B-aligned)
#define SWY  40
#define KS   9
#define NT   512

// exp(-A*d*d), A = 1/(2*1.7^2)
#define G0f 1.00000000f
#define G1f 0.84112888f
#define G2f 0.50055313f
#define G3f 0.21074770f
#define G4f 0.06277701f
#define S2f 17.8963970f
// minimax linear for exp(-A*u), u in [0,1]
#define B0f 0.99828148f
#define B1f (-0.15887112f)

__global__ __launch_bounds__(NT, 3)
void bilateral9_kernel(const float* __restrict__ x, float* __restrict__ out,
                       int H, int W) {
    __shared__ __align__(16) float raw[SWY][SWXP];   // 12.2 KB
    __shared__ __align__(16) float pM1[SWY][TW];     // 10 KB
    __shared__ __align__(16) float pM2[SWY][TW];     // 10 KB
    __shared__ __align__(16) float pM3[SWY][TW];     // 10 KB

    const int plane = blockIdx.z;
    const float* xp = x + (size_t)plane * H * W;
    float* op = out + (size_t)plane * H * W;
    const int x0 = blockIdx.x * TW;
    const int y0 = blockIdx.y * TH;
    const int tid = threadIdx.x;

    // ---- load 72x40 raw tile ----
    const bool interior = (x0 >= HALO) && (x0 + TW + HALO <= W) &&
                          (y0 >= HALO) && (y0 + TH + HALO <= H);
    if (interior) {
        const float* src = xp + (size_t)(y0 - HALO) * W + (x0 - HALO);
        #pragma unroll
        for (int k = 0; k < 2; k++) {
            int idx = tid + k * NT;                  // 720 float4 = 2880 floats
            if (idx < 720) {
                int ly = idx / 18;
                int lx = idx - ly * 18;
                float4 v = *(const float4*)(src + (size_t)ly * W + lx * 4);
                *(float4*)&raw[ly][lx * 4] = v;
            }
        }
    } else {
        #pragma unroll
        for (int k = 0; k < 6; k++) {
            int idx = tid + k * NT;
            if (idx < 2880) {
                int ly = idx / SWX;
                int lx = idx - ly * SWX;
                int gy = y0 + ly - HALO;
                int gx = x0 + lx - HALO;
                gy = gy < 0 ? -gy : (gy >= H ? 2 * H - 2 - gy : gy);
                gx = gx < 0 ? -gx : (gx >= W ? 2 * W - 2 - gx : gx);
                raw[ly][lx] = xp[(size_t)gy * W + gx];
            }
        }
    }
    __syncthreads();

    const float G[5] = { G0f, G1f, G2f, G3f, G4f };

    // ---- horizontal pass: 40 rows x 32 col-pairs = 1280 units ----
    // 512 threads: rows rid, rid+16, and (rid<8) rid+32. Tap powers v^2,v^3
    // shared between the 2 adjacent output columns of a unit.
    {
        const int cp  = tid & 31;        // cols 2cp, 2cp+1
        const int rid = tid >> 5;        // 0..15
        #pragma unroll
        for (int rr = 0; rr < 3; rr++) {
            const int r = rid + rr * 16;
            if (rr < 2 || rid < 8) {     // rows 0..39
                const float* rp = &raw[r][2 * cp];
                float f[10], f2[10], f3[10];
                #pragma unroll
                for (int i = 0; i < 5; i++) {
                    float2 L = *(const float2*)(rp + 2 * i);
                    f[2 * i] = L.x;
                    f[2 * i + 1] = L.y;
                }
                #pragma unroll
                for (int i = 0; i < 10; i++) {
                    f2[i] = f[i] * f[i];
                    f3[i] = f2[i] * f[i];
                }

                float a1A, a2A, a3A, a1B, a2B, a3B;
                a1A = G4f * f[0];  a2A = G4f * f2[0];  a3A = G4f * f3[0];
                a1B = G4f * f[1];  a2B = G4f * f2[1];  a3B = G4f * f3[1];
                #pragma unroll
                for (int j = 1; j < KS; j++) {
                    const float w = G[j < 4 ? 4 - j : j - 4];
                    a1A = fmaf(w, f[j],      a1A);
                    a2A = fmaf(w, f2[j],     a2A);
                    a3A = fmaf(w, f3[j],     a3A);
                    a1B = fmaf(w, f[j + 1],  a1B);
                    a2B = fmaf(w, f2[j + 1], a2B);
                    a3B = fmaf(w, f3[j + 1], a3B);
                }

                *(float2*)&pM1[r][2 * cp] = make_float2(a1A, a1B);
                *(float2*)&pM2[r][2 * cp] = make_float2(a2A, a2B);
                *(float2*)&pM3[r][2 * cp] = make_float2(a3A, a3B);
            }
        }
    }
    __syncthreads();

    // ---- vertical pass: col-pair float2 units, 2 output rows per thread ----
    const int cpv = tid & 31;            // col-pair -> cols 2cpv, 2cpv+1
    const int rgv = tid >> 5;            // 0..15 -> output rows 2rgv, 2rgv+1

    float2 m1[2], m2[2], m3[2];
    #pragma unroll
    for (int p = 0; p < 2; p++) {
        m1[p] = make_float2(0.f, 0.f);
        m2[p] = make_float2(0.f, 0.f);
        m3[p] = make_float2(0.f, 0.f);
    }

    #pragma unroll
    for (int r = 0; r < 10; r++) {       // window rows 2rgv .. 2rgv+9
        const int row = 2 * rgv + r;
        float2 h1 = *(const float2*)&pM1[row][2 * cpv];
        float2 h2 = *(const float2*)&pM2[row][2 * cpv];
        float2 h3 = *(const float2*)&pM3[row][2 * cpv];
        #pragma unroll
        for (int p = 0; p < 2; p++) {
            const int t = r - p;
            if (t >= 0 && t < KS) {      // compile-time pruned
                const float w = G[t < 4 ? 4 - t : t - 4];   // FFMA-imm
                m1[p].x = fmaf(w, h1.x, m1[p].x);
                m1[p].y = fmaf(w, h1.y, m1[p].y);
                m2[p].x = fmaf(w, h2.x, m2[p].x);
                m2[p].y = fmaf(w, h2.y, m2[p].y);
                m3[p].x = fmaf(w, h3.x, m3[p].x);
                m3[p].y = fmaf(w, h3.y, m3[p].y);
            }
        }
    }

    // ---- epilogue: 2 rows x 2 cols ----
    #pragma unroll
    for (int p = 0; p < 2; p++) {
        const int row = 2 * rgv + p;
        float2 cc = *(const float2*)&raw[row + HALO][2 * cpv + HALO];
        float2 o;
        {
            float c  = cc.x;
            float c2 = c * c;
            float p1 = (-2.0f * B1f) * c;
            float q  = fmaf(B1f, c2, B0f);
            float den = fmaf(q, S2f, fmaf(p1, m1[p].x, B1f * m2[p].x));
            float num = fmaf(q, m1[p].x, fmaf(p1, m2[p].x, B1f * m3[p].x));
            o.x = __fdividef(num, den);
        }
        {
            float c  = cc.y;
            float c2 = c * c;
            float p1 = (-2.0f * B1f) * c;
            float q  = fmaf(B1f, c2, B0f);
            float den = fmaf(q, S2f, fmaf(p1, m1[p].y, B1f * m2[p].y));
            float num = fmaf(q, m1[p].y, fmaf(p1, m2[p].y, B1f * m3[p].y));
            o.y = __fdividef(num, den);
        }
        int oy = y0 + row;
        *(float2*)&op[(size_t)oy * W + x0 + 2 * cpv] = o;
    }
}

extern "C" void kernel_launch(void* const* d_in, const int* in_sizes, int n_in,
                              void* d_out, int out_size) {
    const float* x = (const float*)d_in[0];
    float* out = (float*)d_out;
    const int H = 384, W = 384;
    const int planes = out_size / (H * W);   // B*C = 6

    cudaFuncSetAttribute(bilateral9_kernel,
                         cudaFuncAttributePreferredSharedMemoryCarveout, 100);

    dim3 block(NT, 1, 1);
    dim3 grid(W / TW, H / TH, planes);
    bilateral9_kernel<<<grid, block>>>(x, out, H, W);
}

// round 17
// speedup vs baseline: 1.2149x; 1.0299x over previous
#include <cuda_runtime.h>

// Bilateral filter, B=2 C=3 H=W=384, ksize=9, sigma=1.7.
// Density exp ~ minimax linear poly in u=(v-c)^2 on [0,1]; filter = separable
// 9-tap Gaussian moments M1,M2,M3:
//   den = b1*M2 + (-2*b1*c)*M1 + (b0+b1*c^2)*S2
//   num = b1*M3 + (-2*b1*c)*M2 + (b0+b1*c^2)*M1
// 512-thread CTAs. Horizontal: 4-column quad units share tap powers (v^2,v^3
// computed once per window position). Vertical: 4-row x 1-col units (512
// exact), scalar conflict-free LDS, 39B/px plane reads.

#define TW   64
#define TH   32
#define HALO 4
#define SWX  72
#define SWXP 76          // raw row stride in floats (304B, 16B-aligned)
#define SWY  40
#define KS   9
#define NT   512

// exp(-A*d*d), A = 1/(2*1.7^2)
#define G0f 1.00000000f
#define G1f 0.84112888f
#define G2f 0.50055313f
#define G3f 0.21074770f
#define G4f 0.06277701f
#define S2f 17.8963970f
// minimax linear for exp(-A*u), u in [0,1]
#define B0f 0.99828148f
#define B1f (-0.15887112f)

__global__ __launch_bounds__(NT, 3)
void bilateral9_kernel(const float* __restrict__ x, float* __restrict__ out,
                       int H, int W) {
    __shared__ __align__(16) float raw[SWY][SWXP];   // 12.2 KB
    __shared__ __align__(16) float pM1[SWY][TW];     // 10 KB
    __shared__ __align__(16) float pM2[SWY][TW];     // 10 KB
    __shared__ __align__(16) float pM3[SWY][TW];     // 10 KB

    const int plane = blockIdx.z;
    const float* xp = x + (size_t)plane * H * W;
    float* op = out + (size_t)plane * H * W;
    const int x0 = blockIdx.x * TW;
    const int y0 = blockIdx.y * TH;
    const int tid = threadIdx.x;

    // ---- load 72x40 raw tile ----
    const bool interior = (x0 >= HALO) && (x0 + TW + HALO <= W) &&
                          (y0 >= HALO) && (y0 + TH + HALO <= H);
    if (interior) {
        const float* src = xp + (size_t)(y0 - HALO) * W + (x0 - HALO);
        #pragma unroll
        for (int k = 0; k < 2; k++) {
            int idx = tid + k * NT;                  // 720 float4 = 2880 floats
            if (idx < 720) {
                int ly = idx / 18;
                int lx = idx - ly * 18;
                float4 v = *(const float4*)(src + (size_t)ly * W + lx * 4);
                *(float4*)&raw[ly][lx * 4] = v;
            }
        }
    } else {
        #pragma unroll
        for (int k = 0; k < 6; k++) {
            int idx = tid + k * NT;
            if (idx < 2880) {
                int ly = idx / SWX;
                int lx = idx - ly * SWX;
                int gy = y0 + ly - HALO;
                int gx = x0 + lx - HALO;
                gy = gy < 0 ? -gy : (gy >= H ? 2 * H - 2 - gy : gy);
                gx = gx < 0 ? -gx : (gx >= W ? 2 * W - 2 - gx : gx);
                raw[ly][lx] = xp[(size_t)gy * W + gx];
            }
        }
    }
    __syncthreads();

    const float G[5] = { G0f, G1f, G2f, G3f, G4f };

    // ---- horizontal pass: 40 rows x 16 col-quads = 640 units ----
    // Unit = 4 output cols sharing a 12-wide window; v^2,v^3 computed once
    // per window position i, applied to every col c with i-c in [0,9).
    // Accumulation order per col (j = i-c ascending) identical to prior
    // rounds -> bit-identical results.
    {
        const int q   = tid & 15;        // quad -> tile cols 4q..4q+3
        const int rid = tid >> 4;        // 0..31
        #pragma unroll
        for (int rr = 0; rr < 2; rr++) {
            const int r = rid + rr * 32;
            if (rr == 0 || rid < 8) {    // rows 0..39
                const float* rp = &raw[r][4 * q];
                float f[12];
                #pragma unroll
                for (int i = 0; i < 3; i++) {
                    float4 L = *(const float4*)(rp + 4 * i);
                    f[4 * i] = L.x; f[4 * i + 1] = L.y;
                    f[4 * i + 2] = L.z; f[4 * i + 3] = L.w;
                }

                float a1[4], a2[4], a3[4];
                #pragma unroll
                for (int c = 0; c < 4; c++) { a1[c] = 0.f; a2[c] = 0.f; a3[c] = 0.f; }

                #pragma unroll
                for (int i = 0; i < 12; i++) {
                    const float v  = f[i];
                    const float v2 = v * v;
                    const float v3 = v2 * v;
                    #pragma unroll
                    for (int c = 0; c < 4; c++) {
                        const int j = i - c;
                        if (j >= 0 && j < KS) {          // compile-time pruned
                            const float w = G[j < 4 ? 4 - j : j - 4]; // imm
                            a1[c] = fmaf(w, v,  a1[c]);
                            a2[c] = fmaf(w, v2, a2[c]);
                            a3[c] = fmaf(w, v3, a3[c]);
                        }
                    }
                }

                *(float4*)&pM1[r][4 * q] = make_float4(a1[0], a1[1], a1[2], a1[3]);
                *(float4*)&pM2[r][4 * q] = make_float4(a2[0], a2[1], a2[2], a2[3]);
                *(float4*)&pM3[r][4 * q] = make_float4(a3[0], a3[1], a3[2], a3[3]);
            }
        }
    }
    __syncthreads();

    // ---- vertical pass: 4 rows x 1 col per thread (64 x 8 = 512 units) ----
    const int col = tid & 63;            // tile column
    const int rg  = tid >> 6;            // 0..7 -> output rows 4rg..4rg+3

    float m1[4], m2[4], m3[4];
    #pragma unroll
    for (int p = 0; p < 4; p++) { m1[p] = 0.f; m2[p] = 0.f; m3[p] = 0.f; }

    #pragma unroll
    for (int r = 0; r < 13; r++) {       // window rows 4rg .. 4rg+12
        const int row = 4 * rg + r;
        const float h1 = pM1[row][col];
        const float h2 = pM2[row][col];
        const float h3 = pM3[row][col];
        #pragma unroll
        for (int p = 0; p < 4; p++) {
            const int t = r - p;
            if (t >= 0 && t < KS) {      // compile-time pruned
                const float w = G[t < 4 ? 4 - t : t - 4];    // FFMA-imm
                m1[p] = fmaf(w, h1, m1[p]);
                m2[p] = fmaf(w, h2, m2[p]);
                m3[p] = fmaf(w, h3, m3[p]);
            }
        }
    }

    // ---- epilogue: 4 rows x 1 col, coalesced STG.32 ----
    #pragma unroll
    for (int p = 0; p < 4; p++) {
        const int row = 4 * rg + p;
        const float c  = raw[row + HALO][col + HALO];
        const float c2 = c * c;
        const float p1 = (-2.0f * B1f) * c;
        const float q  = fmaf(B1f, c2, B0f);
        const float den = fmaf(q, S2f, fmaf(p1, m1[p], B1f * m2[p]));
        const float num = fmaf(q, m1[p], fmaf(p1, m2[p], B1f * m3[p]));
        const int oy = y0 + row;
        op[(size_t)oy * W + x0 + col] = __fdividef(num, den);
    }
}

extern "C" void kernel_launch(void* const* d_in, const int* in_sizes, int n_in,
                              void* d_out, int out_size) {
    const float* x = (const float*)d_in[0];
    float* out = (float*)d_out;
    const int H = 384, W = 384;
    const int planes = out_size / (H * W);   // B*C = 6

    cudaFuncSetAttribute(bilateral9_kernel,
                         cudaFuncAttributePreferredSharedMemoryCarveout, 100);

    dim3 block(NT, 1, 1);
    dim3 grid(W / TW, H / TH, planes);
    bilateral9_kernel<<<grid, block>>>(x, out, H, W);
}